// round 1
// baseline (speedup 1.0000x reference)
#include <cuda_runtime.h>
#include <cstdint>

#define N_ATOMS 4096
#define L_WORDS 65536
#define DD 10
#define KS 23

// ---------------- scratch (device globals; no allocation allowed) ----------
__device__ float g_xs[2][N_ATOMS * DD];              // GNN ping-pong
__device__ unsigned long long g_hs[5 * N_ATOMS];     // hs packed as f32x2 pairs, [p][m]
__device__ float g_cnn[2][L_WORDS * DD];             // CNN ping-pong
__device__ float g_comp[DD];
__device__ float g_hatt[DD];
__device__ float g_part[256 * DD];                   // attention partial sums

// ---------------- f32x2 helpers (sm_103a packed fp32) -----------------------
__device__ __forceinline__ unsigned long long pack2(float x, float y) {
    unsigned long long r;
    asm("mov.b64 %0, {%1, %2};" : "=l"(r) : "f"(x), "f"(y));
    return r;
}
__device__ __forceinline__ void unpack2(unsigned long long v, float& x, float& y) {
    asm("mov.b64 {%0, %1}, %2;" : "=f"(x), "=f"(y) : "l"(v));
}
__device__ __forceinline__ void fma2(unsigned long long& d, unsigned long long a,
                                     unsigned long long b) {
    asm("fma.rn.f32x2 %0, %1, %2, %0;" : "+l"(d) : "l"(a), "l"(b));
}

// ---------------- gathers ---------------------------------------------------
__global__ void k_gather_fp(const int* __restrict__ fp, const float* __restrict__ emb) {
    int i = blockIdx.x * blockDim.x + threadIdx.x;
    if (i < N_ATOMS * DD) {
        int n = i / DD, d = i - n * DD;
        g_xs[0][i] = emb[(size_t)fp[n] * DD + d];
    }
}
__global__ void k_gather_w(const int* __restrict__ wd, const float* __restrict__ emb) {
    int i = blockIdx.x * blockDim.x + threadIdx.x;
    if (i < L_WORDS * DD) {
        int n = i / DD, d = i - n * DD;
        g_cnn[0][i] = emb[(size_t)wd[n] * DD + d];
    }
}

// ---------------- GNN: hs = relu(xs @ W^T + b), packed to f32x2 -------------
__global__ void k_hs(int buf, const float* __restrict__ Wg, const float* __restrict__ bg) {
    int m = blockIdx.x * blockDim.x + threadIdx.x;
    if (m >= N_ATOMS) return;
    const float* xin = g_xs[buf] + m * DD;
    float x[DD];
#pragma unroll
    for (int c = 0; c < DD; c++) x[c] = xin[c];
#pragma unroll
    for (int p = 0; p < 5; p++) {
        float h0 = bg[2 * p], h1 = bg[2 * p + 1];
#pragma unroll
        for (int c = 0; c < DD; c++) {
            h0 = fmaf(x[c], Wg[(2 * p) * DD + c], h0);
            h1 = fmaf(x[c], Wg[(2 * p + 1) * DD + c], h1);
        }
        g_hs[p * N_ATOMS + m] = pack2(fmaxf(h0, 0.f), fmaxf(h1, 0.f));
    }
}

// ---------------- GNN: xs_out = xs_in + A @ hs ------------------------------
// 128 blocks x 256 threads. Warp owns 4 rows; lanes stride m (coalesced A).
// hs staged in 160KB dynamic smem as f32x2 pairs [p][m].
__global__ void k_gnn(int buf, const float* __restrict__ A) {
    extern __shared__ unsigned long long sh[];  // 5 * 4096 ull
    int tid = threadIdx.x;
    for (int i = tid; i < 5 * N_ATOMS; i += blockDim.x) sh[i] = g_hs[i];
    __syncthreads();

    int warp = tid >> 5, lane = tid & 31;
    int row0 = blockIdx.x * 32 + warp * 4;
    const float* xin = g_xs[buf];
    float* xout = g_xs[buf ^ 1];

    const float* Ar0 = A + (size_t)(row0 + 0) * N_ATOMS;
    const float* Ar1 = A + (size_t)(row0 + 1) * N_ATOMS;
    const float* Ar2 = A + (size_t)(row0 + 2) * N_ATOMS;
    const float* Ar3 = A + (size_t)(row0 + 3) * N_ATOMS;

    unsigned long long acc[4][5];
#pragma unroll
    for (int r = 0; r < 4; r++)
#pragma unroll
        for (int p = 0; p < 5; p++) acc[r][p] = 0ull;

#pragma unroll 2
    for (int m0 = 0; m0 < N_ATOMS; m0 += 32) {
        int m = m0 + lane;
        float a0 = Ar0[m], a1 = Ar1[m], a2 = Ar2[m], a3 = Ar3[m];
        unsigned long long h[5];
#pragma unroll
        for (int p = 0; p < 5; p++) h[p] = sh[p * N_ATOMS + m];
        unsigned long long v0 = pack2(a0, a0), v1 = pack2(a1, a1);
        unsigned long long v2 = pack2(a2, a2), v3 = pack2(a3, a3);
#pragma unroll
        for (int p = 0; p < 5; p++) {
            fma2(acc[0][p], v0, h[p]);
            fma2(acc[1][p], v1, h[p]);
            fma2(acc[2][p], v2, h[p]);
            fma2(acc[3][p], v3, h[p]);
        }
    }

    float f[4][DD];
#pragma unroll
    for (int r = 0; r < 4; r++)
#pragma unroll
        for (int p = 0; p < 5; p++) unpack2(acc[r][p], f[r][2 * p], f[r][2 * p + 1]);
#pragma unroll
    for (int r = 0; r < 4; r++)
#pragma unroll
        for (int d = 0; d < DD; d++)
#pragma unroll
            for (int o = 16; o > 0; o >>= 1)
                f[r][d] += __shfl_down_sync(0xffffffffu, f[r][d], o);

    if (lane == 0) {
#pragma unroll
        for (int r = 0; r < 4; r++) {
            int row = row0 + r;
#pragma unroll
            for (int d = 0; d < DD; d++)
                xout[row * DD + d] = xin[row * DD + d] + f[r][d];
        }
    }
}

// ---------------- CNN layer --------------------------------------------------
// out[l,j] = relu(b + sum_{dl=0..22, c=0..9} in[l-11+dl, c] * W[dl, 11+c-j])
// Block: 256 threads, 2 rows/thread -> 512 rows/block, 128 blocks.
#define CTHREADS 256
#define CRPT 2
#define CROWS (CTHREADS * CRPT)
__global__ void k_cnn(int buf, const float* __restrict__ Wc, const float* __restrict__ bc,
                      int layer) {
    __shared__ float sIn[(CROWS + 22) * 11];        // pitch 11: conflict-free
    __shared__ unsigned long long sW[KS * 50];      // [dl][c][p] f32x2 over j-pairs
    int tid = threadIdx.x;
    const float* in = g_cnn[buf];
    float* out = g_cnn[buf ^ 1];
    const float* W = Wc + layer * KS * KS;
    float bias = bc[layer];

    for (int i = tid; i < KS * 50; i += CTHREADS) {
        int dl = i / 50, rem = i % 50, c = rem / 5, p = rem % 5;
        float w0 = W[dl * KS + 11 + c - 2 * p];       // j = 2p
        float w1 = W[dl * KS + 11 + c - 2 * p - 1];   // j = 2p+1
        sW[i] = pack2(w0, w1);
    }
    int base = blockIdx.x * CROWS - 11;
    for (int i = tid; i < (CROWS + 22) * DD; i += CTHREADS) {
        int rr = i / DD, c = i - rr * DD;
        int g = base + rr;
        sIn[rr * 11 + c] = (g >= 0 && g < L_WORDS) ? in[g * DD + c] : 0.f;
    }
    __syncthreads();

    unsigned long long b2 = pack2(bias, bias);
    unsigned long long acc[CRPT][5];
#pragma unroll
    for (int r = 0; r < CRPT; r++)
#pragma unroll
        for (int p = 0; p < 5; p++) acc[r][p] = b2;

#pragma unroll 1
    for (int dl = 0; dl < KS; dl++) {
#pragma unroll
        for (int c = 0; c < DD; c++) {
            unsigned long long w[5];
#pragma unroll
            for (int p = 0; p < 5; p++) w[p] = sW[dl * 50 + c * 5 + p];
#pragma unroll
            for (int r = 0; r < CRPT; r++) {
                float x = sIn[(tid + r * CTHREADS + dl) * 11 + c];
                unsigned long long x2 = pack2(x, x);
#pragma unroll
                for (int p = 0; p < 5; p++) fma2(acc[r][p], x2, w[p]);
            }
        }
    }

#pragma unroll
    for (int r = 0; r < CRPT; r++) {
        int grow = blockIdx.x * CROWS + tid + r * CTHREADS;
#pragma unroll
        for (int p = 0; p < 5; p++) {
            float v0, v1;
            unpack2(acc[r][p], v0, v1);
            out[grow * DD + 2 * p] = fmaxf(v0, 0.f);
            out[grow * DD + 2 * p + 1] = fmaxf(v1, 0.f);
        }
    }
}

// ---------------- compound = mean(xs); h = relu(compound @ Watt^T + batt) ----
__global__ void k_comp(int buf, const float* __restrict__ Wat, const float* __restrict__ bat) {
    __shared__ float red[512 * DD];
    int tid = threadIdx.x;
    float acc[DD];
#pragma unroll
    for (int d = 0; d < DD; d++) acc[d] = 0.f;
    const float* xs = g_xs[buf];
    for (int n = tid; n < N_ATOMS; n += 512) {
#pragma unroll
        for (int d = 0; d < DD; d++) acc[d] += xs[n * DD + d];
    }
#pragma unroll
    for (int d = 0; d < DD; d++) red[tid * DD + d] = acc[d];
    __syncthreads();
    for (int s = 256; s > 0; s >>= 1) {
        if (tid < s) {
#pragma unroll
            for (int d = 0; d < DD; d++) red[tid * DD + d] += red[(tid + s) * DD + d];
        }
        __syncthreads();
    }
    if (tid < DD) {
        float comp = red[tid] * (1.f / N_ATOMS);
        g_comp[tid] = comp;
        float hv = bat[tid];
#pragma unroll
        for (int c = 0; c < DD; c++) hv = fmaf(red[c] * (1.f / N_ATOMS), Wat[tid * DD + c], hv);
        g_hatt[tid] = fmaxf(hv, 0.f);
    }
}

// ---------------- attention: per-row hs_p, tanh weight, partial protein sums -
__global__ void k_att(int buf, const float* __restrict__ Wat, const float* __restrict__ bat) {
    __shared__ float red[256 * DD];
    __shared__ float sW[DD * DD], sb[DD], sh[DD];
    int tid = threadIdx.x;
    if (tid < DD * DD) sW[tid] = Wat[tid];
    if (tid < DD) { sb[tid] = bat[tid]; sh[tid] = g_hatt[tid]; }
    __syncthreads();

    int l = blockIdx.x * 256 + tid;
    const float* xp = g_cnn[buf] + l * DD;
    float x[DD];
#pragma unroll
    for (int c = 0; c < DD; c++) x[c] = xp[c];
    float hp[DD];
    float wl = 0.f;
#pragma unroll
    for (int t = 0; t < DD; t++) {
        float v = sb[t];
#pragma unroll
        for (int c = 0; c < DD; c++) v = fmaf(x[c], sW[t * DD + c], v);
        v = fmaxf(v, 0.f);
        hp[t] = v;
        wl = fmaf(sh[t], v, wl);
    }
    wl = tanhf(wl);
#pragma unroll
    for (int d = 0; d < DD; d++) red[tid * DD + d] = wl * hp[d];
    __syncthreads();
    for (int s = 128; s > 0; s >>= 1) {
        if (tid < s) {
#pragma unroll
            for (int d = 0; d < DD; d++) red[tid * DD + d] += red[(tid + s) * DD + d];
        }
        __syncthreads();
    }
    if (tid < DD) g_part[blockIdx.x * DD + tid] = red[tid];
}

// ---------------- final fusion MLP -------------------------------------------
__global__ void k_final(const float* __restrict__ Wout, const float* __restrict__ bout,
                        const float* __restrict__ Wint, const float* __restrict__ bint,
                        float* __restrict__ out) {
    __shared__ float cat[20];
    int tid = threadIdx.x;
    if (tid < DD) cat[tid] = g_comp[tid];
    if (tid >= DD && tid < 20) {
        int d = tid - DD;
        float s = 0.f;
        for (int b = 0; b < 256; b++) s += g_part[b * DD + d];
        cat[tid] = s * (1.f / L_WORDS);
    }
    __syncwarp();
    for (int j = 0; j < 3; j++) {
        float v = 0.f;
        if (tid < 20) {
            v = bout[j * 20 + tid];
            for (int c = 0; c < 20; c++) v = fmaf(cat[c], Wout[j * 400 + tid * 20 + c], v);
            v = fmaxf(v, 0.f);
        }
        __syncwarp();
        if (tid < 20) cat[tid] = v;
        __syncwarp();
    }
    if (tid < 2) {
        float v = bint[tid];
        for (int c = 0; c < 20; c++) v = fmaf(cat[c], Wint[tid * 20 + c], v);
        out[tid] = v;
    }
}

// ---------------- launch ------------------------------------------------------
extern "C" void kernel_launch(void* const* d_in, const int* in_sizes, int n_in,
                              void* d_out, int out_size) {
    const int*   fp    = (const int*)d_in[0];
    const float* A     = (const float*)d_in[1];
    const int*   words = (const int*)d_in[2];
    const float* embf  = (const float*)d_in[3];
    const float* embw  = (const float*)d_in[4];
    const float* Wg    = (const float*)d_in[5];
    const float* bg    = (const float*)d_in[6];
    const float* Wc    = (const float*)d_in[7];
    const float* bc    = (const float*)d_in[8];
    const float* Wat   = (const float*)d_in[9];
    const float* bat   = (const float*)d_in[10];
    const float* Wout  = (const float*)d_in[11];
    const float* bout  = (const float*)d_in[12];
    const float* Wint  = (const float*)d_in[13];
    const float* bint  = (const float*)d_in[14];
    float* out = (float*)d_out;

    cudaFuncSetAttribute(k_gnn, cudaFuncAttributeMaxDynamicSharedMemorySize,
                         5 * N_ATOMS * 8);

    k_gather_fp<<<(N_ATOMS * DD + 255) / 256, 256>>>(fp, embf);
    k_gather_w<<<(L_WORDS * DD + 255) / 256, 256>>>(words, embw);

    int gb = 0;
    for (int i = 0; i < 3; i++) {
        k_hs<<<N_ATOMS / 256, 256>>>(gb, Wg + i * 100, bg + i * 10);
        k_gnn<<<N_ATOMS / 32, 256, 5 * N_ATOMS * 8>>>(gb, A);
        gb ^= 1;
    }

    int cb = 0;
    for (int i = 0; i < 3; i++) {
        k_cnn<<<L_WORDS / CROWS, CTHREADS>>>(cb, Wc, bc, i);
        cb ^= 1;
    }

    k_comp<<<1, 512>>>(gb, Wat, bat);
    k_att<<<L_WORDS / 256, 256>>>(cb, Wat, bat);
    k_final<<<1, 32>>>(Wout, bout, Wint, bint, out);
}

// round 2
// speedup vs baseline: 1.2748x; 1.2748x over previous
#include <cuda_runtime.h>
#include <cstdint>

#define N_ATOMS 4096
#define L_WORDS 65536
#define DD 10
#define KS 23

// ---------------- scratch (device globals; no allocation allowed) ----------
__device__ float g_xs[2][N_ATOMS * DD];              // GNN ping-pong
// hs packed f32x2, layout [k][p][m/4] with k = m&3 (conflict-free for float4 cols)
__device__ unsigned long long g_hs[4 * 5 * (N_ATOMS / 4)];
__device__ float g_cnn[2][L_WORDS * DD];             // CNN ping-pong
__device__ float g_comp[DD];
__device__ float g_hatt[DD];
__device__ float g_part[256 * DD];                   // attention partial sums

// ---------------- f32x2 helpers (sm_103a packed fp32) -----------------------
__device__ __forceinline__ unsigned long long pack2(float x, float y) {
    unsigned long long r;
    asm("mov.b64 %0, {%1, %2};" : "=l"(r) : "f"(x), "f"(y));
    return r;
}
__device__ __forceinline__ void unpack2(unsigned long long v, float& x, float& y) {
    asm("mov.b64 {%0, %1}, %2;" : "=f"(x), "=f"(y) : "l"(v));
}
__device__ __forceinline__ void fma2(unsigned long long& d, unsigned long long a,
                                     unsigned long long b) {
    asm("fma.rn.f32x2 %0, %1, %2, %0;" : "+l"(d) : "l"(a), "l"(b));
}

// ---------------- gathers ---------------------------------------------------
__global__ void k_gather_fp(const int* __restrict__ fp, const float* __restrict__ emb) {
    int i = blockIdx.x * blockDim.x + threadIdx.x;
    if (i < N_ATOMS * DD) {
        int n = i / DD, d = i - n * DD;
        g_xs[0][i] = emb[(size_t)fp[n] * DD + d];
    }
}
__global__ void k_gather_w(const int* __restrict__ wd, const float* __restrict__ emb) {
    int i = blockIdx.x * blockDim.x + threadIdx.x;
    if (i < L_WORDS * DD) {
        int n = i / DD, d = i - n * DD;
        g_cnn[0][i] = emb[(size_t)wd[n] * DD + d];
    }
}

// ---------------- GNN: hs = relu(xs @ W^T + b), packed to f32x2 -------------
__global__ void k_hs(int buf, const float* __restrict__ Wg, const float* __restrict__ bg) {
    int m = blockIdx.x * blockDim.x + threadIdx.x;
    if (m >= N_ATOMS) return;
    const float* xin = g_xs[buf] + m * DD;
    float x[DD];
#pragma unroll
    for (int c = 0; c < DD; c++) x[c] = xin[c];
    int k = m & 3, base = m >> 2;
#pragma unroll
    for (int p = 0; p < 5; p++) {
        float h0 = bg[2 * p], h1 = bg[2 * p + 1];
#pragma unroll
        for (int c = 0; c < DD; c++) {
            h0 = fmaf(x[c], Wg[(2 * p) * DD + c], h0);
            h1 = fmaf(x[c], Wg[(2 * p + 1) * DD + c], h1);
        }
        g_hs[(k * 5 + p) * (N_ATOMS / 4) + base] = pack2(fmaxf(h0, 0.f), fmaxf(h1, 0.f));
    }
}

// ---------------- GNN: xs_out = xs_in + A @ hs ------------------------------
// 128 blocks x 256 threads; warp owns 4 rows; lane covers 4 consecutive m via
// float4 A loads (LDG.128) with next-iteration prefetch. hs staged in smem in
// [k][p][m/4] layout -> LDS.64 conflict-free.
__global__ void k_gnn(int buf, const float* __restrict__ A) {
    extern __shared__ unsigned long long sh[];  // 4*5*1024 ull = 160KB
    int tid = threadIdx.x;
    for (int i = tid; i < 5 * N_ATOMS; i += blockDim.x) sh[i] = g_hs[i];
    __syncthreads();

    int warp = tid >> 5, lane = tid & 31;
    int row0 = blockIdx.x * 32 + warp * 4;
    const float* xin = g_xs[buf];
    float* xout = g_xs[buf ^ 1];

    const float4* A4[4];
#pragma unroll
    for (int r = 0; r < 4; r++)
        A4[r] = (const float4*)(A + (size_t)(row0 + r) * N_ATOMS);

    unsigned long long acc[4][5];
#pragma unroll
    for (int r = 0; r < 4; r++)
#pragma unroll
        for (int p = 0; p < 5; p++) acc[r][p] = 0ull;

    float4 a[4];
#pragma unroll
    for (int r = 0; r < 4; r++) a[r] = A4[r][lane];

    // 32 iterations of 128 columns each
    for (int it = 0; it < N_ATOMS / 128; it++) {
        int q0 = it * 32;  // float4 index base for this iter
        float4 nxt[4];
        if (it + 1 < N_ATOMS / 128) {
#pragma unroll
            for (int r = 0; r < 4; r++) nxt[r] = A4[r][q0 + 32 + lane];
        }
#pragma unroll
        for (int k = 0; k < 4; k++) {
            unsigned long long h[5];
#pragma unroll
            for (int p = 0; p < 5; p++)
                h[p] = sh[(k * 5 + p) * (N_ATOMS / 4) + q0 + lane];
            float av0 = (k == 0) ? a[0].x : (k == 1) ? a[0].y : (k == 2) ? a[0].z : a[0].w;
            float av1 = (k == 0) ? a[1].x : (k == 1) ? a[1].y : (k == 2) ? a[1].z : a[1].w;
            float av2 = (k == 0) ? a[2].x : (k == 1) ? a[2].y : (k == 2) ? a[2].z : a[2].w;
            float av3 = (k == 0) ? a[3].x : (k == 1) ? a[3].y : (k == 2) ? a[3].z : a[3].w;
            unsigned long long v0 = pack2(av0, av0), v1 = pack2(av1, av1);
            unsigned long long v2 = pack2(av2, av2), v3 = pack2(av3, av3);
#pragma unroll
            for (int p = 0; p < 5; p++) {
                fma2(acc[0][p], v0, h[p]);
                fma2(acc[1][p], v1, h[p]);
                fma2(acc[2][p], v2, h[p]);
                fma2(acc[3][p], v3, h[p]);
            }
        }
#pragma unroll
        for (int r = 0; r < 4; r++) a[r] = nxt[r];
    }

    float f[4][DD];
#pragma unroll
    for (int r = 0; r < 4; r++)
#pragma unroll
        for (int p = 0; p < 5; p++) unpack2(acc[r][p], f[r][2 * p], f[r][2 * p + 1]);
#pragma unroll
    for (int r = 0; r < 4; r++)
#pragma unroll
        for (int d = 0; d < DD; d++)
#pragma unroll
            for (int o = 16; o > 0; o >>= 1)
                f[r][d] += __shfl_down_sync(0xffffffffu, f[r][d], o);

    if (lane == 0) {
#pragma unroll
        for (int r = 0; r < 4; r++) {
            int row = row0 + r;
#pragma unroll
            for (int d = 0; d < DD; d++)
                xout[row * DD + d] = xin[row * DD + d] + f[r][d];
        }
    }
}

// ---------------- CNN layer --------------------------------------------------
// out[l,j] = relu(b + sum_{dl=0..22, c=0..9} in[l-11+dl, c] * W[dl, 11+c-j])
#define CTHREADS 256
#define CRPT 2
#define CROWS (CTHREADS * CRPT)
__global__ void k_cnn(int buf, const float* __restrict__ Wc, const float* __restrict__ bc,
                      int layer) {
    __shared__ float sIn[(CROWS + 22) * 11];        // pitch 11: conflict-free
    __shared__ unsigned long long sW[KS * 50];      // [dl][c][p] f32x2 over j-pairs
    int tid = threadIdx.x;
    const float* in = g_cnn[buf];
    float* out = g_cnn[buf ^ 1];
    const float* W = Wc + layer * KS * KS;
    float bias = bc[layer];

    for (int i = tid; i < KS * 50; i += CTHREADS) {
        int dl = i / 50, rem = i % 50, c = rem / 5, p = rem % 5;
        float w0 = W[dl * KS + 11 + c - 2 * p];       // j = 2p
        float w1 = W[dl * KS + 11 + c - 2 * p - 1];   // j = 2p+1
        sW[i] = pack2(w0, w1);
    }
    int base = blockIdx.x * CROWS - 11;
    for (int i = tid; i < (CROWS + 22) * DD; i += CTHREADS) {
        int rr = i / DD, c = i - rr * DD;
        int g = base + rr;
        sIn[rr * 11 + c] = (g >= 0 && g < L_WORDS) ? in[g * DD + c] : 0.f;
    }
    __syncthreads();

    unsigned long long b2 = pack2(bias, bias);
    unsigned long long acc[CRPT][5];
#pragma unroll
    for (int r = 0; r < CRPT; r++)
#pragma unroll
        for (int p = 0; p < 5; p++) acc[r][p] = b2;

#pragma unroll 1
    for (int dl = 0; dl < KS; dl++) {
#pragma unroll
        for (int c = 0; c < DD; c++) {
            unsigned long long w[5];
#pragma unroll
            for (int p = 0; p < 5; p++) w[p] = sW[dl * 50 + c * 5 + p];
#pragma unroll
            for (int r = 0; r < CRPT; r++) {
                float x = sIn[(tid + r * CTHREADS + dl) * 11 + c];
                unsigned long long x2 = pack2(x, x);
#pragma unroll
                for (int p = 0; p < 5; p++) fma2(acc[r][p], x2, w[p]);
            }
        }
    }

#pragma unroll
    for (int r = 0; r < CRPT; r++) {
        int grow = blockIdx.x * CROWS + tid + r * CTHREADS;
#pragma unroll
        for (int p = 0; p < 5; p++) {
            float v0, v1;
            unpack2(acc[r][p], v0, v1);
            out[grow * DD + 2 * p] = fmaxf(v0, 0.f);
            out[grow * DD + 2 * p + 1] = fmaxf(v1, 0.f);
        }
    }
}

// ---------------- compound = mean(xs); h = relu(compound @ Watt^T + batt) ----
__global__ void k_comp(int buf, const float* __restrict__ Wat, const float* __restrict__ bat) {
    __shared__ float red[512 * DD];
    int tid = threadIdx.x;
    float acc[DD];
#pragma unroll
    for (int d = 0; d < DD; d++) acc[d] = 0.f;
    const float* xs = g_xs[buf];
    for (int n = tid; n < N_ATOMS; n += 512) {
#pragma unroll
        for (int d = 0; d < DD; d++) acc[d] += xs[n * DD + d];
    }
#pragma unroll
    for (int d = 0; d < DD; d++) red[tid * DD + d] = acc[d];
    __syncthreads();
    for (int s = 256; s > 0; s >>= 1) {
        if (tid < s) {
#pragma unroll
            for (int d = 0; d < DD; d++) red[tid * DD + d] += red[(tid + s) * DD + d];
        }
        __syncthreads();
    }
    if (tid < DD) {
        float comp = red[tid] * (1.f / N_ATOMS);
        g_comp[tid] = comp;
        float hv = bat[tid];
#pragma unroll
        for (int c = 0; c < DD; c++) hv = fmaf(red[c] * (1.f / N_ATOMS), Wat[tid * DD + c], hv);
        g_hatt[tid] = fmaxf(hv, 0.f);
    }
}

// ---------------- attention: per-row hs_p, tanh weight, partial protein sums -
__global__ void k_att(int buf, const float* __restrict__ Wat, const float* __restrict__ bat) {
    __shared__ float red[256 * DD];
    __shared__ float sW[DD * DD], sb[DD], sh[DD];
    int tid = threadIdx.x;
    if (tid < DD * DD) sW[tid] = Wat[tid];
    if (tid < DD) { sb[tid] = bat[tid]; sh[tid] = g_hatt[tid]; }
    __syncthreads();

    int l = blockIdx.x * 256 + tid;
    const float* xp = g_cnn[buf] + l * DD;
    float x[DD];
#pragma unroll
    for (int c = 0; c < DD; c++) x[c] = xp[c];
    float hp[DD];
    float wl = 0.f;
#pragma unroll
    for (int t = 0; t < DD; t++) {
        float v = sb[t];
#pragma unroll
        for (int c = 0; c < DD; c++) v = fmaf(x[c], sW[t * DD + c], v);
        v = fmaxf(v, 0.f);
        hp[t] = v;
        wl = fmaf(sh[t], v, wl);
    }
    wl = tanhf(wl);
#pragma unroll
    for (int d = 0; d < DD; d++) red[tid * DD + d] = wl * hp[d];
    __syncthreads();
    for (int s = 128; s > 0; s >>= 1) {
        if (tid < s) {
#pragma unroll
            for (int d = 0; d < DD; d++) red[tid * DD + d] += red[(tid + s) * DD + d];
        }
        __syncthreads();
    }
    if (tid < DD) g_part[blockIdx.x * DD + tid] = red[tid];
}

// ---------------- final fusion MLP -------------------------------------------
__global__ void k_final(const float* __restrict__ Wout, const float* __restrict__ bout,
                        const float* __restrict__ Wint, const float* __restrict__ bint,
                        float* __restrict__ out) {
    __shared__ float cat[20];
    int tid = threadIdx.x;
    if (tid < DD) cat[tid] = g_comp[tid];
    if (tid >= DD && tid < 20) {
        int d = tid - DD;
        float s = 0.f;
        for (int b = 0; b < 256; b++) s += g_part[b * DD + d];
        cat[tid] = s * (1.f / L_WORDS);
    }
    __syncwarp();
    for (int j = 0; j < 3; j++) {
        float v = 0.f;
        if (tid < 20) {
            v = bout[j * 20 + tid];
            for (int c = 0; c < 20; c++) v = fmaf(cat[c], Wout[j * 400 + tid * 20 + c], v);
            v = fmaxf(v, 0.f);
        }
        __syncwarp();
        if (tid < 20) cat[tid] = v;
        __syncwarp();
    }
    if (tid < 2) {
        float v = bint[tid];
        for (int c = 0; c < 20; c++) v = fmaf(cat[c], Wint[tid * 20 + c], v);
        out[tid] = v;
    }
}

// ---------------- launch ------------------------------------------------------
extern "C" void kernel_launch(void* const* d_in, const int* in_sizes, int n_in,
                              void* d_out, int out_size) {
    const int*   fp    = (const int*)d_in[0];
    const float* A     = (const float*)d_in[1];
    const int*   words = (const int*)d_in[2];
    const float* embf  = (const float*)d_in[3];
    const float* embw  = (const float*)d_in[4];
    const float* Wg    = (const float*)d_in[5];
    const float* bg    = (const float*)d_in[6];
    const float* Wc    = (const float*)d_in[7];
    const float* bc    = (const float*)d_in[8];
    const float* Wat   = (const float*)d_in[9];
    const float* bat   = (const float*)d_in[10];
    const float* Wout  = (const float*)d_in[11];
    const float* bout  = (const float*)d_in[12];
    const float* Wint  = (const float*)d_in[13];
    const float* bint  = (const float*)d_in[14];
    float* out = (float*)d_out;

    cudaFuncSetAttribute(k_gnn, cudaFuncAttributeMaxDynamicSharedMemorySize,
                         5 * N_ATOMS * 8);

    k_gather_fp<<<(N_ATOMS * DD + 255) / 256, 256>>>(fp, embf);
    k_gather_w<<<(L_WORDS * DD + 255) / 256, 256>>>(words, embw);

    int gb = 0;
    for (int i = 0; i < 3; i++) {
        k_hs<<<N_ATOMS / 256, 256>>>(gb, Wg + i * 100, bg + i * 10);
        k_gnn<<<N_ATOMS / 32, 256, 5 * N_ATOMS * 8>>>(gb, A);
        gb ^= 1;
    }

    int cb = 0;
    for (int i = 0; i < 3; i++) {
        k_cnn<<<L_WORDS / CROWS, CTHREADS>>>(cb, Wc, bc, i);
        cb ^= 1;
    }

    k_comp<<<1, 512>>>(gb, Wat, bat);
    k_att<<<L_WORDS / 256, 256>>>(cb, Wat, bat);
    k_final<<<1, 32>>>(Wout, bout, Wint, bint, out);
}

// round 3
// speedup vs baseline: 1.4101x; 1.1061x over previous
#include <cuda_runtime.h>
#include <cstdint>

#define N_ATOMS 4096
#define L_WORDS 65536
#define DD 10
#define KS 23
#define KSPLIT 2
#define KCHUNK (N_ATOMS / KSPLIT)   // 2048 columns per k-block

// ---------------- scratch (device globals; no allocation allowed) ----------
__device__ float g_xs[2][N_ATOMS * DD];              // GNN xs ping-pong
// hs packed f32x2, layout [k4][p][m/4] with k4 = m&3 (conflict-free float4 cols)
__device__ unsigned long long g_hs[4 * 5 * (N_ATOMS / 4)];
__device__ float g_pp[KSPLIT][N_ATOMS * DD];         // split-K partials of A@hs
__device__ float g_cnn[2][L_WORDS * DD];             // CNN ping-pong
__device__ float g_comp[DD];
__device__ float g_hatt[DD];
__device__ float g_part[256 * DD];                   // attention partial sums

// ---------------- f32x2 helpers (sm_103a packed fp32) -----------------------
__device__ __forceinline__ unsigned long long pack2(float x, float y) {
    unsigned long long r;
    asm("mov.b64 %0, {%1, %2};" : "=l"(r) : "f"(x), "f"(y));
    return r;
}
__device__ __forceinline__ void unpack2(unsigned long long v, float& x, float& y) {
    asm("mov.b64 {%0, %1}, %2;" : "=f"(x), "=f"(y) : "l"(v));
}
__device__ __forceinline__ void fma2(unsigned long long& d, unsigned long long a,
                                     unsigned long long b) {
    asm("fma.rn.f32x2 %0, %1, %2, %0;" : "+l"(d) : "l"(a), "l"(b));
}

// ---------------- gathers ---------------------------------------------------
__global__ void k_gather_fp(const int* __restrict__ fp, const float* __restrict__ emb) {
    int i = blockIdx.x * blockDim.x + threadIdx.x;
    if (i < N_ATOMS * DD) {
        int n = i / DD, d = i - n * DD;
        g_xs[0][i] = emb[(size_t)fp[n] * DD + d];
    }
}
__global__ void k_gather_w(const int* __restrict__ wd, const float* __restrict__ emb) {
    int i = blockIdx.x * blockDim.x + threadIdx.x;
    if (i < L_WORDS * DD) {
        int n = i / DD, d = i - n * DD;
        g_cnn[0][i] = emb[(size_t)wd[n] * DD + d];
    }
}

// ---------------- GNN: (optional combine) + hs = relu(xs @ W^T + b) ---------
// If addp != 0: xs_out = xs_in + P0 + P1 (written back); hs computed from xs_out.
__global__ void k_hs(int inbuf, int outbuf, int addp,
                     const float* __restrict__ Wg, const float* __restrict__ bg) {
    int m = blockIdx.x * blockDim.x + threadIdx.x;
    if (m >= N_ATOMS) return;
    float x[DD];
#pragma unroll
    for (int c = 0; c < DD; c++) {
        float v = g_xs[inbuf][m * DD + c];
        if (addp) {
            v += g_pp[0][m * DD + c] + g_pp[1][m * DD + c];
            g_xs[outbuf][m * DD + c] = v;
        }
        x[c] = v;
    }
    int k4 = m & 3, base = m >> 2;
#pragma unroll
    for (int p = 0; p < 5; p++) {
        float h0 = bg[2 * p], h1 = bg[2 * p + 1];
#pragma unroll
        for (int c = 0; c < DD; c++) {
            h0 = fmaf(x[c], Wg[(2 * p) * DD + c], h0);
            h1 = fmaf(x[c], Wg[(2 * p + 1) * DD + c], h1);
        }
        g_hs[(k4 * 5 + p) * (N_ATOMS / 4) + base] = pack2(fmaxf(h0, 0.f), fmaxf(h1, 0.f));
    }
}

// ---------------- GNN: P[kb] = A[:, kb-chunk] @ hs[kb-chunk] ----------------
// Grid (128 row-blocks, 2 k-blocks) x 256 threads. Warp owns 4 rows; lane does
// 4 consecutive k via LDG.128 + prefetch. hs chunk (80KB) in smem -> 2 CTA/SM.
__global__ void k_gnn(const float* __restrict__ A) {
    extern __shared__ unsigned long long sh[];  // 4*5*512 ull = 80KB
    int tid = threadIdx.x;
    int kb = blockIdx.y;
    // load hs chunk: smem [k4][p][512], global [k4][p][1024] offset kb*512
    for (int i = tid; i < 20 * (KCHUNK / 4); i += blockDim.x) {
        int kp = i / (KCHUNK / 4), j = i % (KCHUNK / 4);
        sh[kp * (KCHUNK / 4) + j] = g_hs[kp * (N_ATOMS / 4) + kb * (KCHUNK / 4) + j];
    }
    __syncthreads();

    int warp = tid >> 5, lane = tid & 31;
    int row0 = blockIdx.x * 32 + warp * 4;
    float* pout = g_pp[kb];

    const float4* A4[4];
#pragma unroll
    for (int r = 0; r < 4; r++)
        A4[r] = (const float4*)(A + (size_t)(row0 + r) * N_ATOMS) + kb * (KCHUNK / 4);

    unsigned long long acc[4][5];
#pragma unroll
    for (int r = 0; r < 4; r++)
#pragma unroll
        for (int p = 0; p < 5; p++) acc[r][p] = 0ull;

    float4 a[4];
#pragma unroll
    for (int r = 0; r < 4; r++) a[r] = A4[r][lane];

    // 16 iterations of 128 columns each
    for (int it = 0; it < KCHUNK / 128; it++) {
        int q0 = it * 32;  // float4 index base within chunk
        float4 nxt[4];
        if (it + 1 < KCHUNK / 128) {
#pragma unroll
            for (int r = 0; r < 4; r++) nxt[r] = A4[r][q0 + 32 + lane];
        }
#pragma unroll
        for (int k = 0; k < 4; k++) {
            unsigned long long h[5];
#pragma unroll
            for (int p = 0; p < 5; p++)
                h[p] = sh[(k * 5 + p) * (KCHUNK / 4) + q0 + lane];
            float av0 = (k == 0) ? a[0].x : (k == 1) ? a[0].y : (k == 2) ? a[0].z : a[0].w;
            float av1 = (k == 0) ? a[1].x : (k == 1) ? a[1].y : (k == 2) ? a[1].z : a[1].w;
            float av2 = (k == 0) ? a[2].x : (k == 1) ? a[2].y : (k == 2) ? a[2].z : a[2].w;
            float av3 = (k == 0) ? a[3].x : (k == 1) ? a[3].y : (k == 2) ? a[3].z : a[3].w;
            unsigned long long v0 = pack2(av0, av0), v1 = pack2(av1, av1);
            unsigned long long v2 = pack2(av2, av2), v3 = pack2(av3, av3);
#pragma unroll
            for (int p = 0; p < 5; p++) {
                fma2(acc[0][p], v0, h[p]);
                fma2(acc[1][p], v1, h[p]);
                fma2(acc[2][p], v2, h[p]);
                fma2(acc[3][p], v3, h[p]);
            }
        }
#pragma unroll
        for (int r = 0; r < 4; r++) a[r] = nxt[r];
    }

    float f[4][DD];
#pragma unroll
    for (int r = 0; r < 4; r++)
#pragma unroll
        for (int p = 0; p < 5; p++) unpack2(acc[r][p], f[r][2 * p], f[r][2 * p + 1]);
#pragma unroll
    for (int r = 0; r < 4; r++)
#pragma unroll
        for (int d = 0; d < DD; d++)
#pragma unroll
            for (int o = 16; o > 0; o >>= 1)
                f[r][d] += __shfl_down_sync(0xffffffffu, f[r][d], o);

    if (lane == 0) {
#pragma unroll
        for (int r = 0; r < 4; r++) {
            int row = row0 + r;
#pragma unroll
            for (int d = 0; d < DD; d++)
                pout[row * DD + d] = f[r][d];
        }
    }
}

// ---------------- CNN layer --------------------------------------------------
// out[l,j] = relu(b + sum_{dl=0..22, c=0..9} in[l-11+dl, c] * W[dl, 11+c-j])
#define CTHREADS 256
#define CRPT 2
#define CROWS (CTHREADS * CRPT)
__global__ void k_cnn(int buf, const float* __restrict__ Wc, const float* __restrict__ bc,
                      int layer) {
    __shared__ float sIn[(CROWS + 22) * 11];        // pitch 11: conflict-free
    __shared__ unsigned long long sW[KS * 50];      // [dl][c][p] f32x2 over j-pairs
    int tid = threadIdx.x;
    const float* in = g_cnn[buf];
    float* out = g_cnn[buf ^ 1];
    const float* W = Wc + layer * KS * KS;
    float bias = bc[layer];

    for (int i = tid; i < KS * 50; i += CTHREADS) {
        int dl = i / 50, rem = i % 50, c = rem / 5, p = rem % 5;
        float w0 = W[dl * KS + 11 + c - 2 * p];       // j = 2p
        float w1 = W[dl * KS + 11 + c - 2 * p - 1];   // j = 2p+1
        sW[i] = pack2(w0, w1);
    }
    int base = blockIdx.x * CROWS - 11;
    for (int i = tid; i < (CROWS + 22) * DD; i += CTHREADS) {
        int rr = i / DD, c = i - rr * DD;
        int g = base + rr;
        sIn[rr * 11 + c] = (g >= 0 && g < L_WORDS) ? in[g * DD + c] : 0.f;
    }
    __syncthreads();

    unsigned long long b2 = pack2(bias, bias);
    unsigned long long acc[CRPT][5];
#pragma unroll
    for (int r = 0; r < CRPT; r++)
#pragma unroll
        for (int p = 0; p < 5; p++) acc[r][p] = b2;

#pragma unroll 1
    for (int dl = 0; dl < KS; dl++) {
#pragma unroll
        for (int c = 0; c < DD; c++) {
            unsigned long long w[5];
#pragma unroll
            for (int p = 0; p < 5; p++) w[p] = sW[dl * 50 + c * 5 + p];
#pragma unroll
            for (int r = 0; r < CRPT; r++) {
                float x = sIn[(tid + r * CTHREADS + dl) * 11 + c];
                unsigned long long x2 = pack2(x, x);
#pragma unroll
                for (int p = 0; p < 5; p++) fma2(acc[r][p], x2, w[p]);
            }
        }
    }

#pragma unroll
    for (int r = 0; r < CRPT; r++) {
        int grow = blockIdx.x * CROWS + tid + r * CTHREADS;
#pragma unroll
        for (int p = 0; p < 5; p++) {
            float v0, v1;
            unpack2(acc[r][p], v0, v1);
            out[grow * DD + 2 * p] = fmaxf(v0, 0.f);
            out[grow * DD + 2 * p + 1] = fmaxf(v1, 0.f);
        }
    }
}

// ---------------- compound = mean(xs2 + P0 + P1); h = relu(comp@Watt^T+batt) -
__global__ void k_comp(int buf, const float* __restrict__ Wat, const float* __restrict__ bat) {
    __shared__ float red[512 * DD];
    int tid = threadIdx.x;
    float acc[DD];
#pragma unroll
    for (int d = 0; d < DD; d++) acc[d] = 0.f;
    const float* xs = g_xs[buf];
    for (int n = tid; n < N_ATOMS; n += 512) {
#pragma unroll
        for (int d = 0; d < DD; d++)
            acc[d] += xs[n * DD + d] + g_pp[0][n * DD + d] + g_pp[1][n * DD + d];
    }
#pragma unroll
    for (int d = 0; d < DD; d++) red[tid * DD + d] = acc[d];
    __syncthreads();
    for (int s = 256; s > 0; s >>= 1) {
        if (tid < s) {
#pragma unroll
            for (int d = 0; d < DD; d++) red[tid * DD + d] += red[(tid + s) * DD + d];
        }
        __syncthreads();
    }
    if (tid < DD) {
        float comp = red[tid] * (1.f / N_ATOMS);
        g_comp[tid] = comp;
        float hv = bat[tid];
#pragma unroll
        for (int c = 0; c < DD; c++) hv = fmaf(red[c] * (1.f / N_ATOMS), Wat[tid * DD + c], hv);
        g_hatt[tid] = fmaxf(hv, 0.f);
    }
}

// ---------------- attention: per-row hs_p, tanh weight, partial protein sums -
__global__ void k_att(int buf, const float* __restrict__ Wat, const float* __restrict__ bat) {
    __shared__ float red[256 * DD];
    __shared__ float sW[DD * DD], sb[DD], sh[DD];
    int tid = threadIdx.x;
    if (tid < DD * DD) sW[tid] = Wat[tid];
    if (tid < DD) { sb[tid] = bat[tid]; sh[tid] = g_hatt[tid]; }
    __syncthreads();

    int l = blockIdx.x * 256 + tid;
    const float* xp = g_cnn[buf] + l * DD;
    float x[DD];
#pragma unroll
    for (int c = 0; c < DD; c++) x[c] = xp[c];
    float hp[DD];
    float wl = 0.f;
#pragma unroll
    for (int t = 0; t < DD; t++) {
        float v = sb[t];
#pragma unroll
        for (int c = 0; c < DD; c++) v = fmaf(x[c], sW[t * DD + c], v);
        v = fmaxf(v, 0.f);
        hp[t] = v;
        wl = fmaf(sh[t], v, wl);
    }
    wl = tanhf(wl);
#pragma unroll
    for (int d = 0; d < DD; d++) red[tid * DD + d] = wl * hp[d];
    __syncthreads();
    for (int s = 128; s > 0; s >>= 1) {
        if (tid < s) {
#pragma unroll
            for (int d = 0; d < DD; d++) red[tid * DD + d] += red[(tid + s) * DD + d];
        }
        __syncthreads();
    }
    if (tid < DD) g_part[blockIdx.x * DD + tid] = red[tid];
}

// ---------------- final fusion MLP -------------------------------------------
__global__ void k_final(const float* __restrict__ Wout, const float* __restrict__ bout,
                        const float* __restrict__ Wint, const float* __restrict__ bint,
                        float* __restrict__ out) {
    __shared__ float cat[20];
    int tid = threadIdx.x;
    if (tid < DD) cat[tid] = g_comp[tid];
    if (tid >= DD && tid < 20) {
        int d = tid - DD;
        float s = 0.f;
        for (int b = 0; b < 256; b++) s += g_part[b * DD + d];
        cat[tid] = s * (1.f / L_WORDS);
    }
    __syncwarp();
    for (int j = 0; j < 3; j++) {
        float v = 0.f;
        if (tid < 20) {
            v = bout[j * 20 + tid];
            for (int c = 0; c < 20; c++) v = fmaf(cat[c], Wout[j * 400 + tid * 20 + c], v);
            v = fmaxf(v, 0.f);
        }
        __syncwarp();
        if (tid < 20) cat[tid] = v;
        __syncwarp();
    }
    if (tid < 2) {
        float v = bint[tid];
        for (int c = 0; c < 20; c++) v = fmaf(cat[c], Wint[tid * 20 + c], v);
        out[tid] = v;
    }
}

// ---------------- launch ------------------------------------------------------
extern "C" void kernel_launch(void* const* d_in, const int* in_sizes, int n_in,
                              void* d_out, int out_size) {
    const int*   fp    = (const int*)d_in[0];
    const float* A     = (const float*)d_in[1];
    const int*   words = (const int*)d_in[2];
    const float* embf  = (const float*)d_in[3];
    const float* embw  = (const float*)d_in[4];
    const float* Wg    = (const float*)d_in[5];
    const float* bg    = (const float*)d_in[6];
    const float* Wc    = (const float*)d_in[7];
    const float* bc    = (const float*)d_in[8];
    const float* Wat   = (const float*)d_in[9];
    const float* bat   = (const float*)d_in[10];
    const float* Wout  = (const float*)d_in[11];
    const float* bout  = (const float*)d_in[12];
    const float* Wint  = (const float*)d_in[13];
    const float* bint  = (const float*)d_in[14];
    float* out = (float*)d_out;

    const int smem = 20 * (KCHUNK / 4) * 8;  // 80KB
    cudaFuncSetAttribute(k_gnn, cudaFuncAttributeMaxDynamicSharedMemorySize, smem);

    k_gather_fp<<<(N_ATOMS * DD + 255) / 256, 256>>>(fp, embf);
    k_gather_w<<<(L_WORDS * DD + 255) / 256, 256>>>(words, embw);

    dim3 ggrid(N_ATOMS / 32, KSPLIT);
    // layer 0: hs from xs0 (buf0), no partial add
    k_hs<<<N_ATOMS / 256, 256>>>(0, 0, 0, Wg + 0 * 100, bg + 0 * 10);
    k_gnn<<<ggrid, 256, smem>>>(A);
    // layer 1: xs1 = xs0 + P -> buf1
    k_hs<<<N_ATOMS / 256, 256>>>(0, 1, 1, Wg + 1 * 100, bg + 1 * 10);
    k_gnn<<<ggrid, 256, smem>>>(A);
    // layer 2: xs2 = xs1 + P -> buf0
    k_hs<<<N_ATOMS / 256, 256>>>(1, 0, 1, Wg + 2 * 100, bg + 2 * 10);
    k_gnn<<<ggrid, 256, smem>>>(A);
    // xs3 = xs2 + P folded into k_comp

    int cb = 0;
    for (int i = 0; i < 3; i++) {
        k_cnn<<<L_WORDS / CROWS, CTHREADS>>>(cb, Wc, bc, i);
        cb ^= 1;
    }

    k_comp<<<1, 512>>>(0, Wat, bat);
    k_att<<<L_WORDS / 256, 256>>>(cb, Wat, bat);
    k_final<<<1, 32>>>(Wout, bout, Wint, bint, out);
}